// round 2
// baseline (speedup 1.0000x reference)
#include <cuda_runtime.h>
#include <math.h>

#define Bz 4
#define Nz 2048
#define Dz 4096
#define Oz 4096
#define Rz 128
#define Ez 4
#define Pz 2

// Scratch (no allocations allowed)
__device__ __align__(16) float g_proj[Bz*Nz*Rz];    // 4 MB
__device__ __align__(16) float g_delta[Bz*Nz*Rz];   // 4 MB
__device__ __align__(16) float g_A[Bz*Rz*Rz];       // 256 KB

// ---------------------------------------------------------------------------
// Setup: per-batch combined matrix A_b[r,k] = mask[b,r] * (M_b[r,k] - delta_rk)
// M_b[r,k] = sum_e ew[b,e] * gains[b,e,k] * chart_e[r,k]
// chart_e = H(v1)H(v0) = I - 2 v0 v0^T - 2 v1 v1^T + 4 (v1.v0) v1 v0^T
// ---------------------------------------------------------------------------
__global__ __launch_bounds__(256) void setup_kernel(
    const float* __restrict__ logits, const float* __restrict__ mask,
    const float* __restrict__ gains,  const float* __restrict__ refl)
{
    __shared__ float s_v[Ez*Pz*Rz];
    __shared__ float s_inorm[Ez*Pz];
    __shared__ float s_c[Ez];
    __shared__ float s_ew[Ez];
    const int b = blockIdx.x;
    const int tid = threadIdx.x;

    for (int i = tid; i < Ez*Pz*Rz; i += 256) s_v[i] = refl[i];
    __syncthreads();
    if (tid < Ez*Pz) {
        float ss = 0.f;
        const float* v = s_v + tid*Rz;
        for (int r = 0; r < Rz; r++) ss += v[r]*v[r];
        s_inorm[tid] = 1.f / fmaxf(sqrtf(ss), 1e-6f);
    }
    __syncthreads();
    for (int i = tid; i < Ez*Pz*Rz; i += 256) s_v[i] *= s_inorm[i >> 7];
    __syncthreads();
    if (tid < Ez) {
        float c = 0.f;
        const float* v0 = s_v + (tid*Pz + 0)*Rz;
        const float* v1 = s_v + (tid*Pz + 1)*Rz;
        for (int r = 0; r < Rz; r++) c += v0[r]*v1[r];
        s_c[tid] = c;
    }
    if (tid == 0) {
        float m = -1e30f;
        for (int e = 0; e < Ez; e++) m = fmaxf(m, logits[b*Ez + e]);
        float t[Ez], s = 0.f;
        for (int e = 0; e < Ez; e++) { t[e] = expf(2.f*(logits[b*Ez+e]-m)); s += t[e]; }
        for (int e = 0; e < Ez; e++) s_ew[e] = t[e] / s;
    }
    __syncthreads();

    for (int idx = tid; idx < Rz*Rz; idx += 256) {
        const int r = idx >> 7, k = idx & (Rz-1);
        const float del = (r == k) ? 1.f : 0.f;
        float sum = 0.f;
        #pragma unroll
        for (int e = 0; e < Ez; e++) {
            const float v0r = s_v[(e*Pz+0)*Rz + r], v0k = s_v[(e*Pz+0)*Rz + k];
            const float v1r = s_v[(e*Pz+1)*Rz + r], v1k = s_v[(e*Pz+1)*Rz + k];
            const float chart = del - 2.f*v0r*v0k - 2.f*v1r*v1k + 4.f*s_c[e]*v1r*v0k;
            sum += s_ew[e] * gains[(b*Ez+e)*Rz + k] * chart;
        }
        g_A[(b*Rz + r)*Rz + k] = mask[b*Rz + r] * (sum - del);
    }
}

// ---------------------------------------------------------------------------
// GEMM1: proj[8192,128] = x[8192,4096] @ basis[128,4096]^T
// Tile 64(M) x 128(N), K-chunks of 16, 256 threads, 4x8 microtile
// ---------------------------------------------------------------------------
__global__ __launch_bounds__(256) void gemm1_kernel(
    const float* __restrict__ x, const float* __restrict__ basis)
{
    __shared__ float As[16][66];    // [k][m] transposed, pad 2 -> conflict-free stores
    __shared__ float Bs[16][132];   // [k][n] transposed, pad 4 keeps 16B alignment

    const int tid = threadIdx.x;
    const int m0 = blockIdx.x * 64;
    const int ty = tid >> 4, tx = tid & 15;

    float acc[4][8];
    #pragma unroll
    for (int i = 0; i < 4; i++)
        #pragma unroll
        for (int j = 0; j < 8; j++) acc[i][j] = 0.f;

    const int a_r = tid >> 2;
    const int a_k = (tid & 3) << 2;
    const float* xrow = x + (long)(m0 + a_r)*Dz + a_k;
    const int b_r0 = tid >> 2;
    const int b_k0 = (tid & 3) << 2;
    const float* brow0 = basis + (long)b_r0*Dz + b_k0;
    const int b_r1 = (tid + 256) >> 2;
    const float* brow1 = basis + (long)b_r1*Dz + b_k0;

    for (int k0 = 0; k0 < Dz; k0 += 16) {
        const float4 av  = *(const float4*)(xrow + k0);
        const float4 bv0 = *(const float4*)(brow0 + k0);
        const float4 bv1 = *(const float4*)(brow1 + k0);
        As[b_k0+0][a_r] = av.x; As[b_k0+1][a_r] = av.y;
        As[b_k0+2][a_r] = av.z; As[b_k0+3][a_r] = av.w;
        Bs[b_k0+0][b_r0] = bv0.x; Bs[b_k0+1][b_r0] = bv0.y;
        Bs[b_k0+2][b_r0] = bv0.z; Bs[b_k0+3][b_r0] = bv0.w;
        Bs[b_k0+0][b_r1] = bv1.x; Bs[b_k0+1][b_r1] = bv1.y;
        Bs[b_k0+2][b_r1] = bv1.z; Bs[b_k0+3][b_r1] = bv1.w;
        __syncthreads();
        #pragma unroll
        for (int k = 0; k < 16; k++) {
            float a[4], bb[8];
            #pragma unroll
            for (int j = 0; j < 4; j++) a[j] = As[k][ty*4 + j];
            *(float4*)&bb[0] = *(const float4*)&Bs[k][tx*8];
            *(float4*)&bb[4] = *(const float4*)&Bs[k][tx*8 + 4];
            #pragma unroll
            for (int i = 0; i < 4; i++)
                #pragma unroll
                for (int j = 0; j < 8; j++) acc[i][j] = fmaf(a[i], bb[j], acc[i][j]);
        }
        __syncthreads();
    }
    #pragma unroll
    for (int i = 0; i < 4; i++) {
        const int row = m0 + ty*4 + i;
        float* p = g_proj + (long)row*Rz + tx*8;
        *(float4*)p       = make_float4(acc[i][0], acc[i][1], acc[i][2], acc[i][3]);
        *(float4*)(p + 4) = make_float4(acc[i][4], acc[i][5], acc[i][6], acc[i][7]);
    }
}

// ---------------------------------------------------------------------------
// delta[8192,128] = proj[8192,128] @ A_b[128,128]  (per-batch A)
// Tile 128x128, K=128 in chunks of 16, 256 threads, 8x8 microtile
// ---------------------------------------------------------------------------
__global__ __launch_bounds__(256) void delta_kernel()
{
    __shared__ float As[16][130];
    __shared__ float Bs[16][132];
    const int tid = threadIdx.x;
    const int m0 = blockIdx.x * 128;
    const int b = m0 / Nz;
    const int ty = tid >> 4, tx = tid & 15;
    const float* Ab = g_A + b*Rz*Rz;

    float acc[8][8];
    #pragma unroll
    for (int i = 0; i < 8; i++)
        #pragma unroll
        for (int j = 0; j < 8; j++) acc[i][j] = 0.f;

    for (int k0 = 0; k0 < Rz; k0 += 16) {
        #pragma unroll
        for (int l = 0; l < 2; l++) {
            const int lin = tid + l*256;
            const int r = lin >> 2;
            const int kk = (lin & 3) << 2;
            float4 v = *(const float4*)(g_proj + (long)(m0 + r)*Rz + k0 + kk);
            As[kk+0][r] = v.x; As[kk+1][r] = v.y; As[kk+2][r] = v.z; As[kk+3][r] = v.w;
        }
        #pragma unroll
        for (int l = 0; l < 2; l++) {
            const int lin = tid + l*256;
            const int kk = lin >> 5;
            const int n = (lin & 31) << 2;
            *(float4*)&Bs[kk][n] = *(const float4*)(Ab + (k0 + kk)*Rz + n);
        }
        __syncthreads();
        #pragma unroll
        for (int k = 0; k < 16; k++) {
            float a[8], bb[8];
            #pragma unroll
            for (int j = 0; j < 8; j++) a[j] = As[k][ty*8 + j];
            *(float4*)&bb[0] = *(const float4*)&Bs[k][tx*8];
            *(float4*)&bb[4] = *(const float4*)&Bs[k][tx*8 + 4];
            #pragma unroll
            for (int i = 0; i < 8; i++)
                #pragma unroll
                for (int j = 0; j < 8; j++) acc[i][j] = fmaf(a[i], bb[j], acc[i][j]);
        }
        __syncthreads();
    }
    #pragma unroll
    for (int i = 0; i < 8; i++) {
        const int row = m0 + ty*8 + i;
        float* p = g_delta + (long)row*Rz + tx*8;
        *(float4*)p       = make_float4(acc[i][0], acc[i][1], acc[i][2], acc[i][3]);
        *(float4*)(p + 4) = make_float4(acc[i][4], acc[i][5], acc[i][6], acc[i][7]);
    }
}

// ---------------------------------------------------------------------------
// GEMM2: out[8192,4096] = delta[8192,128] @ W[128,4096]
// Tile 128x128, K=128 in chunks of 16, 256 threads, 8x8 microtile
// ---------------------------------------------------------------------------
__global__ __launch_bounds__(256) void gemm2_kernel(
    const float* __restrict__ W, float* __restrict__ out)
{
    __shared__ float As[16][130];
    __shared__ float Bs[16][132];
    const int tid = threadIdx.x;
    const int m0 = blockIdx.y * 128;
    const int n0 = blockIdx.x * 128;
    const int ty = tid >> 4, tx = tid & 15;

    float acc[8][8];
    #pragma unroll
    for (int i = 0; i < 8; i++)
        #pragma unroll
        for (int j = 0; j < 8; j++) acc[i][j] = 0.f;

    for (int k0 = 0; k0 < Rz; k0 += 16) {
        #pragma unroll
        for (int l = 0; l < 2; l++) {
            const int lin = tid + l*256;
            const int r = lin >> 2;
            const int kk = (lin & 3) << 2;
            float4 v = *(const float4*)(g_delta + (long)(m0 + r)*Rz + k0 + kk);
            As[kk+0][r] = v.x; As[kk+1][r] = v.y; As[kk+2][r] = v.z; As[kk+3][r] = v.w;
        }
        #pragma unroll
        for (int l = 0; l < 2; l++) {
            const int lin = tid + l*256;
            const int kk = lin >> 5;
            const int n = (lin & 31) << 2;
            *(float4*)&Bs[kk][n] = *(const float4*)(W + (long)(k0 + kk)*Oz + n0 + n);
        }
        __syncthreads();
        #pragma unroll
        for (int k = 0; k < 16; k++) {
            float a[8], bb[8];
            #pragma unroll
            for (int j = 0; j < 8; j++) a[j] = As[k][ty*8 + j];
            *(float4*)&bb[0] = *(const float4*)&Bs[k][tx*8];
            *(float4*)&bb[4] = *(const float4*)&Bs[k][tx*8 + 4];
            #pragma unroll
            for (int i = 0; i < 8; i++)
                #pragma unroll
                for (int j = 0; j < 8; j++) acc[i][j] = fmaf(a[i], bb[j], acc[i][j]);
        }
        __syncthreads();
    }
    #pragma unroll
    for (int i = 0; i < 8; i++) {
        const int row = m0 + ty*8 + i;
        float* p = out + (long)row*Oz + n0 + tx*8;
        *(float4*)p       = make_float4(acc[i][0], acc[i][1], acc[i][2], acc[i][3]);
        *(float4*)(p + 4) = make_float4(acc[i][4], acc[i][5], acc[i][6], acc[i][7]);
    }
}

// ---------------------------------------------------------------------------
extern "C" void kernel_launch(void* const* d_in, const int* in_sizes, int n_in,
                              void* d_out, int out_size)
{
    const float* x      = (const float*)d_in[0];  // [B,N,D]
    const float* logits = (const float*)d_in[1];  // [B,E]
    const float* mask   = (const float*)d_in[2];  // [B,R]
    const float* gains  = (const float*)d_in[3];  // [B,E,R]
    const float* ibasis = (const float*)d_in[4];  // [R,D]
    const float* obasis = (const float*)d_in[5];  // [R,O]
    const float* refl   = (const float*)d_in[6];  // [E,P,R]
    float* out = (float*)d_out;                   // [B,N,O]

    setup_kernel<<<Bz, 256>>>(logits, mask, gains, refl);
    gemm1_kernel<<<(Bz*Nz)/64, 256>>>(x, ibasis);
    delta_kernel<<<(Bz*Nz)/128, 256>>>();
    gemm2_kernel<<<dim3(Oz/128, (Bz*Nz)/128), 256>>>(obasis, out);
}

// round 6
// speedup vs baseline: 3.0213x; 3.0213x over previous
#include <cuda_runtime.h>
#include <cuda_bf16.h>
#include <cstdint>
#include <math.h>

#define Bz 4
#define Nz 2048
#define Dz 4096
#define Oz 4096
#define Rz 128
#define Ez 4
#define Pz 2

// ---------------- global scratch (device globals; no allocs allowed) -------
__device__ __align__(16) unsigned g_bh[128*2048];   // basis hi  [128][4096]bf16 -> words [128][2048]
__device__ __align__(16) unsigned g_bl[128*2048];   // basis lo
__device__ __align__(16) unsigned g_wh[4096*64];    // W^T hi    [4096][128]bf16 -> words [4096][64]
__device__ __align__(16) unsigned g_wl[4096*64];
__device__ __align__(16) unsigned g_ph[8192*64];    // proj hi   [8192][128]bf16
__device__ __align__(16) unsigned g_pl[8192*64];
__device__ __align__(16) unsigned g_dh[8192*64];    // delta hi
__device__ __align__(16) unsigned g_dl[8192*64];
__device__ __align__(16) unsigned g_abth[4*128*64]; // A_b^T hi  [b][n=128][r=128]bf16
__device__ __align__(16) unsigned g_abtl[4*128*64];

// ---------------- helpers ----------------
__device__ __forceinline__ unsigned short bfbits(float f){
    unsigned short u; asm("cvt.rn.bf16.f32 %0, %1;" : "=h"(u) : "f"(f)); return u;
}
__device__ __forceinline__ float bf2f(unsigned short u){
    return __uint_as_float(((unsigned)u)<<16);
}
__device__ __forceinline__ void split2(float a, float b, unsigned &hi, unsigned &lo){
    unsigned short ha=bfbits(a), hb=bfbits(b);
    hi = (unsigned)ha | ((unsigned)hb<<16);
    unsigned short la=bfbits(a - bf2f(ha)), lb=bfbits(b - bf2f(hb));
    lo = (unsigned)la | ((unsigned)lb<<16);
}
__device__ __forceinline__ unsigned smem_u32(const void* p){
    unsigned a; asm("{ .reg .u64 t; cvta.to.shared.u64 t, %1; cvt.u32.u64 %0, t; }" : "=r"(a) : "l"(p));
    return a;
}
__device__ __forceinline__ void mma16816(float d[4], const unsigned a[4], const unsigned b[2]){
    asm volatile("mma.sync.aligned.m16n8k16.row.col.f32.bf16.bf16.f32 "
        "{%0,%1,%2,%3}, {%4,%5,%6,%7}, {%8,%9}, {%0,%1,%2,%3};"
        : "+f"(d[0]), "+f"(d[1]), "+f"(d[2]), "+f"(d[3])
        : "r"(a[0]), "r"(a[1]), "r"(a[2]), "r"(a[3]), "r"(b[0]), "r"(b[1]));
}
// A fragment (16x16): a0=(g,2t), a1=(g+8,2t), a2=(g,2t+8), a3=(g+8,2t+8); smem stride 72 halves
__device__ __forceinline__ void ldfragA(unsigned a[4], const unsigned short* As, int row, int kk, int g, int tig){
    const unsigned short* p = As + (row + g)*72 + kk + 2*tig;
    a[0] = *(const unsigned*)p;
    a[1] = *(const unsigned*)(p + 8*72);
    a[2] = *(const unsigned*)(p + 8);
    a[3] = *(const unsigned*)(p + 8*72 + 8);
}
// B fragment (16kx8n), B stored [n][k]: b0=(k=2t,n=g), b1=(k=2t+8,n=g)
__device__ __forceinline__ void ldfragB(unsigned b[2], const unsigned short* Bs, int n, int kk, int g, int tig){
    const unsigned short* p = Bs + (n + g)*72 + kk + 2*tig;
    b[0] = *(const unsigned*)p;
    b[1] = *(const unsigned*)(p + 8);
}
__device__ __forceinline__ void cpasync16(unsigned saddr, const void* gp){
    asm volatile("cp.async.cg.shared.global [%0], [%1], 16;" :: "r"(saddr), "l"(gp));
}

// ---------------------------------------------------------------------------
// setup: A_b^T[n][r] = mask[r]*(sum_e ew*gains[b,e,n]*chart_e[r,n] - delta_rn)
// written as bf16 hi/lo words (pairs along r)
// ---------------------------------------------------------------------------
__global__ __launch_bounds__(256) void setup_kernel(
    const float* __restrict__ logits, const float* __restrict__ mask,
    const float* __restrict__ gains,  const float* __restrict__ refl)
{
    __shared__ float s_v[Ez*Pz*Rz];
    __shared__ float s_inorm[Ez*Pz];
    __shared__ float s_c[Ez], s_ew[Ez], s_m[Rz], s_g[Ez*Rz];
    const int b = blockIdx.x;
    const int tid = threadIdx.x;

    for (int i = tid; i < Ez*Pz*Rz; i += 256) s_v[i] = refl[i];
    for (int i = tid; i < Rz; i += 256) s_m[i] = mask[b*Rz + i];
    for (int i = tid; i < Ez*Rz; i += 256) s_g[i] = gains[b*Ez*Rz + i];
    __syncthreads();
    if (tid < Ez*Pz) {
        float ss = 0.f;
        const float* v = s_v + tid*Rz;
        for (int r = 0; r < Rz; r++) ss += v[r]*v[r];
        s_inorm[tid] = 1.f / fmaxf(sqrtf(ss), 1e-6f);
    }
    __syncthreads();
    for (int i = tid; i < Ez*Pz*Rz; i += 256) s_v[i] *= s_inorm[i >> 7];
    __syncthreads();
    if (tid < Ez) {
        float c = 0.f;
        const float* v0 = s_v + (tid*Pz+0)*Rz;
        const float* v1 = s_v + (tid*Pz+1)*Rz;
        for (int r = 0; r < Rz; r++) c += v0[r]*v1[r];
        s_c[tid] = c;
    }
    if (tid == 0) {
        float m = -1e30f;
        for (int e = 0; e < Ez; e++) m = fmaxf(m, logits[b*Ez + e]);
        float t[Ez], s = 0.f;
        for (int e = 0; e < Ez; e++) { t[e] = expf(2.f*(logits[b*Ez+e]-m)); s += t[e]; }
        for (int e = 0; e < Ez; e++) s_ew[e] = t[e] / s;
    }
    __syncthreads();

    for (int j = 0; j < 32; j++) {
        const int idx = tid + j*256;     // 8192 = 128n * 64 r-pairs
        const int n = idx >> 6;
        const int t = idx & 63;
        float val[2];
        #pragma unroll
        for (int q = 0; q < 2; q++) {
            const int r = 2*t + q;
            const float del = (r == n) ? 1.f : 0.f;
            float sum = 0.f;
            #pragma unroll
            for (int e = 0; e < Ez; e++) {
                const float v0r = s_v[(e*Pz+0)*Rz + r], v0n = s_v[(e*Pz+0)*Rz + n];
                const float v1r = s_v[(e*Pz+1)*Rz + r], v1n = s_v[(e*Pz+1)*Rz + n];
                const float chart = del - 2.f*v0r*v0n - 2.f*v1r*v1n + 4.f*s_c[e]*v1r*v0n;
                sum += s_ew[e] * s_g[e*Rz + n] * chart;
            }
            val[q] = s_m[r] * (sum - del);
        }
        unsigned hi, lo; split2(val[0], val[1], hi, lo);
        g_abth[b*8192 + n*64 + t] = hi;
        g_abtl[b*8192 + n*64 + t] = lo;
    }
}

// ---------------------------------------------------------------------------
// conv_basis: basis[128][4096] fp32 -> g_bh/g_bl bf16 (elementwise split)
// ---------------------------------------------------------------------------
__global__ __launch_bounds__(256) void conv_basis_kernel(const float* __restrict__ bas)
{
    const int idx4 = blockIdx.x*256 + threadIdx.x;   // 131072 float4
    const float4 v = ((const float4*)bas)[idx4];
    unsigned h0,l0,h1,l1;
    split2(v.x, v.y, h0, l0);
    split2(v.z, v.w, h1, l1);
    ((uint2*)g_bh)[idx4] = make_uint2(h0, h1);
    ((uint2*)g_bl)[idx4] = make_uint2(l0, l1);
}

// ---------------------------------------------------------------------------
// conv_w: W[128][4096] fp32 -> W^T bf16 hi/lo [4096][128]. grid 64, n0=blk*64
// ---------------------------------------------------------------------------
__global__ __launch_bounds__(256) void conv_w_kernel(const float* __restrict__ w)
{
    __shared__ float s_in[128*68];
    const int tid = threadIdx.x;
    const int n0 = blockIdx.x * 64;
    #pragma unroll
    for (int t = 0; t < 8; t++) {
        const int idx = tid + t*256;          // 2048 float4
        const int row = idx >> 4;             // k
        const int seg = idx & 15;             // 16 float4 per 64-col row
        *(float4*)&s_in[row*68 + seg*4] = *(const float4*)(w + (long)row*Oz + n0 + seg*4);
    }
    __syncthreads();
    #pragma unroll
    for (int t8 = 0; t8 < 16; t8++) {
        const int idx = tid + t8*256;         // 4096 word outputs
        const int n = idx >> 6;
        const int t = idx & 63;               // k pair
        unsigned hi, lo;
        split2(s_in[(2*t)*68 + n], s_in[(2*t+1)*68 + n], hi, lo);
        g_wh[(long)(n0+n)*64 + t] = hi;
        g_wl[(long)(n0+n)*64 + t] = lo;
    }
}

// ---------------------------------------------------------------------------
// GEMM1: proj = x[8192][4096] @ basis^T -> split bf16 g_ph/g_pl
// tile 64m x 128n, kc=64, cp.async double-buffered B, reg-prefetched x
// smem halves: A bufs 2x(4608h+4608l), B bufs 2x(9216h+9216l) = 55296 halves
// ---------------------------------------------------------------------------
#define G1_SMEM (55296*2)
__global__ __launch_bounds__(256) void gemm1_kernel(const float* __restrict__ x)
{
    extern __shared__ unsigned short sm[];
    const unsigned sbase = smem_u32(sm);
    const int tid = threadIdx.x;
    const int wid = tid >> 5;
    const int lane = tid & 31;
    const int g = lane >> 2, tig = lane & 3;
    const int wm = wid & 1, wn = wid >> 1;
    const long m0 = (long)blockIdx.x * 64;

    float acc[2][4][4];
    #pragma unroll
    for (int mt = 0; mt < 2; mt++)
        #pragma unroll
        for (int nt = 0; nt < 4; nt++)
            #pragma unroll
            for (int q = 0; q < 4; q++) acc[mt][nt][q] = 0.f;

    float4 xr[4];
    // x load geometry: 64 rows x 16 float4
    const int xrow = tid >> 4, xseg = tid & 15;
    const float* xbase = x + (m0 + xrow)*Dz + xseg*4;

    // B cp.async geometry: 128 rows x 8 uint4 (per hi/lo)
    const int brow = tid >> 3, bseg = tid & 7;

    // preload chunk 0
    #pragma unroll
    for (int t = 0; t < 4; t++) xr[t] = *(const float4*)(xbase + (t*16)*Dz);
    {
        const unsigned sB = sbase + (18432)*2;
        #pragma unroll
        for (int t = 0; t < 4; t++) {
            const int row = brow + t*32;
            cpasync16(sB + (row*72 + bseg*8)*2,        g_bh + (long)row*2048 + bseg*4);
            cpasync16(sB + 9216*2 + (row*72 + bseg*8)*2, g_bl + (long)row*2048 + bseg*4);
        }
        asm volatile("cp.async.commit_group;" ::: "memory");
    }

    for (int i = 0; i < 64; i++) {
        const int buf = i & 1;
        if (i < 63) {
            const unsigned sB = sbase + (18432 + (buf^1)*18432)*2;
            #pragma unroll
            for (int t = 0; t < 4; t++) {
                const int row = brow + t*32;
                cpasync16(sB + (row*72 + bseg*8)*2,          g_bh + (long)row*2048 + (i+1)*32 + bseg*4);
                cpasync16(sB + 9216*2 + (row*72 + bseg*8)*2, g_bl + (long)row*2048 + (i+1)*32 + bseg*4);
            }
            asm volatile("cp.async.commit_group;" ::: "memory");
        }
        // convert x chunk i into A smem
        {
            unsigned short* Ab = sm + buf*9216;
            #pragma unroll
            for (int t = 0; t < 4; t++) {
                const int row = xrow + t*16;
                unsigned h0,l0,h1,l1;
                split2(xr[t].x, xr[t].y, h0, l0);
                split2(xr[t].z, xr[t].w, h1, l1);
                *(uint2*)&Ab[row*72 + xseg*4]        = make_uint2(h0, h1);
                *(uint2*)&Ab[4608 + row*72 + xseg*4] = make_uint2(l0, l1);
            }
        }
        // prefetch x chunk i+1
        if (i < 63) {
            #pragma unroll
            for (int t = 0; t < 4; t++) xr[t] = *(const float4*)(xbase + (t*16)*Dz + (i+1)*64);
        }
        if (i < 63) asm volatile("cp.async.wait_group 1;" ::: "memory");
        else        asm volatile("cp.async.wait_group 0;" ::: "memory");
        __syncthreads();

        const unsigned short* Abase = sm + buf*9216;
        const unsigned short* Bbase = sm + 18432 + buf*18432;
        #pragma unroll
        for (int kk = 0; kk < 64; kk += 16) {
            #pragma unroll
            for (int p = 0; p < 3; p++) {
                const unsigned short* As = Abase + ((p==2) ? 4608 : 0);
                const unsigned short* Bs = Bbase + ((p==1) ? 9216 : 0);
                unsigned a[2][4], bb[4][2];
                #pragma unroll
                for (int mt = 0; mt < 2; mt++) ldfragA(a[mt], As, wm*32 + mt*16, kk, g, tig);
                #pragma unroll
                for (int nt = 0; nt < 4; nt++) ldfragB(bb[nt], Bs, wn*32 + nt*8, kk, g, tig);
                #pragma unroll
                for (int mt = 0; mt < 2; mt++)
                    #pragma unroll
                    for (int nt = 0; nt < 4; nt++) mma16816(acc[mt][nt], a[mt], bb[nt]);
            }
        }
        __syncthreads();
    }

    // epilogue: split proj to g_ph/g_pl
    #pragma unroll
    for (int mt = 0; mt < 2; mt++)
        #pragma unroll
        for (int nt = 0; nt < 4; nt++) {
            const long r0 = m0 + wm*32 + mt*16 + g;
            const int col2 = wn*16 + nt*4 + tig;
            unsigned hi, lo;
            split2(acc[mt][nt][0], acc[mt][nt][1], hi, lo);
            g_ph[r0*64 + col2] = hi; g_pl[r0*64 + col2] = lo;
            split2(acc[mt][nt][2], acc[mt][nt][3], hi, lo);
            g_ph[(r0+8)*64 + col2] = hi; g_pl[(r0+8)*64 + col2] = lo;
        }
}

// ---------------------------------------------------------------------------
// generic 128x128 K=128 split-3 mma body used by delta and gemm2
// smem: AH 0, AL 9216, BH 18432, BL 27648 (halves), 73728 bytes
// ---------------------------------------------------------------------------
#define G2_SMEM (36864*2)

__device__ __forceinline__ void mma_128x128_body(
    unsigned short* sm, float acc[4][4][4],
    const unsigned* __restrict__ Ah, const unsigned* __restrict__ Al, long arow0,
    const unsigned* __restrict__ Bh, const unsigned* __restrict__ Bl, long brow0,
    int tid, int wm, int wn, int g, int tig)
{
    const int row = tid >> 3, seg = tid & 7;
    for (int c = 0; c < 2; c++) {
        #pragma unroll
        for (int t = 0; t < 4; t++) {
            const int r = row + t*32;
            *(uint4*)&sm[r*72 + seg*8]         = *(const uint4*)(Ah + (arow0 + r)*64 + c*32 + seg*4);
            *(uint4*)&sm[9216 + r*72 + seg*8]  = *(const uint4*)(Al + (arow0 + r)*64 + c*32 + seg*4);
            *(uint4*)&sm[18432 + r*72 + seg*8] = *(const uint4*)(Bh + (brow0 + r)*64 + c*32 + seg*4);
            *(uint4*)&sm[27648 + r*72 + seg*8] = *(const uint4*)(Bl + (brow0 + r)*64 + c*32 + seg*4);
        }
        __syncthreads();
        #pragma unroll
        for (int kk = 0; kk < 64; kk += 16) {
            #pragma unroll
            for (int p = 0; p < 3; p++) {
                const unsigned short* As = sm + ((p==2) ? 9216 : 0);
                const unsigned short* Bs = sm + 18432 + ((p==1) ? 9216 : 0);
                unsigned a[4][4], bb[4][2];
                #pragma unroll
                for (int mt = 0; mt < 4; mt++) ldfragA(a[mt], As, wm*64 + mt*16, kk, g, tig);
                #pragma unroll
                for (int nt = 0; nt < 4; nt++) ldfragB(bb[nt], Bs, wn*32 + nt*8, kk, g, tig);
                #pragma unroll
                for (int mt = 0; mt < 4; mt++)
                    #pragma unroll
                    for (int nt = 0; nt < 4; nt++) mma16816(acc[mt][nt], a[mt], bb[nt]);
            }
        }
        __syncthreads();
    }
}

// delta = proj @ A_b^T -> split bf16 g_dh/g_dl ; grid 64
__global__ __launch_bounds__(256) void delta_kernel()
{
    extern __shared__ unsigned short sm[];
    const int tid = threadIdx.x;
    const int wid = tid >> 5, lane = tid & 31;
    const int g = lane >> 2, tig = lane & 3;
    const int wm = wid & 1, wn = wid >> 1;
    const int mtile = blockIdx.x;
    const long m0 = (long)mtile * 128;
    const int b = mtile >> 4;

    float acc[4][4][4];
    #pragma unroll
    for (int mt = 0; mt < 4; mt++)
        #pragma unroll
        for (int nt = 0; nt < 4; nt++)
            #pragma unroll
            for (int q = 0; q < 4; q++) acc[mt][nt][q] = 0.f;

    mma_128x128_body(sm, acc, g_ph, g_pl, m0, g_abth + (long)b*8192, g_abtl + (long)b*8192, 0,
                     tid, wm, wn, g, tig);

    #pragma unroll
    for (int mt = 0; mt < 4; mt++)
        #pragma unroll
        for (int nt = 0; nt < 4; nt++) {
            const long r0 = m0 + wm*64 + mt*16 + g;
            const int col2 = wn*16 + nt*4 + tig;
            unsigned hi, lo;
            split2(acc[mt][nt][0], acc[mt][nt][1], hi, lo);
            g_dh[r0*64 + col2] = hi; g_dl[r0*64 + col2] = lo;
            split2(acc[mt][nt][2], acc[mt][nt][3], hi, lo);
            g_dh[(r0+8)*64 + col2] = hi; g_dl[(r0+8)*64 + col2] = lo;
        }
}

// gemm2: out = delta @ W  via wT tiles; grid (32 n, 64 m)
__global__ __launch_bounds__(256) void gemm2_kernel(float* __restrict__ out)
{
    extern __shared__ unsigned short sm[];
    const int tid = threadIdx.x;
    const int wid = tid >> 5, lane = tid & 31;
    const int g = lane >> 2, tig = lane & 3;
    const int wm = wid & 1, wn = wid >> 1;
    const long m0 = (long)blockIdx.y * 128;
    const long n0 = (long)blockIdx.x * 128;

    float acc[4][4][4];
    #pragma unroll
    for (int mt = 0; mt < 4; mt++)
        #pragma unroll
        for (int nt = 0; nt < 4; nt++)
            #pragma unroll
            for (int q = 0; q < 4; q++) acc[mt][nt][q] = 0.f;

    mma_128x128_body(sm, acc, g_dh, g_dl, m0, g_wh, g_wl, n0, tid, wm, wn, g, tig);

    // stage fp32 tile in smem for coalesced store
    float* s_out = (float*)sm;
    #pragma unroll
    for (int mt = 0; mt < 4; mt++)
        #pragma unroll
        for (int nt = 0; nt < 4; nt++) {
            const int lr = wm*64 + mt*16 + g;
            const int lc = wn*32 + nt*8 + 2*tig;
            *(float2*)&s_out[lr*132 + lc]     = make_float2(acc[mt][nt][0], acc[mt][nt][1]);
            *(float2*)&s_out[(lr+8)*132 + lc] = make_float2(acc[mt][nt][2], acc[mt][nt][3]);
        }
    __syncthreads();
    #pragma unroll
    for (int t = 0; t < 16; t++) {
        const int idx = tid + t*256;       // 4096 float4
        const int row = idx >> 5;
        const int seg = idx & 31;
        *(float4*)(out + (m0 + row)*Oz + n0 + seg*4) = *(const float4*)&s_out[row*132 + seg*4];
    }
}

// ---------------------------------------------------------------------------
extern "C" void kernel_launch(void* const* d_in, const int* in_sizes, int n_in,
                              void* d_out, int out_size)
{
    const float* x      = (const float*)d_in[0];
    const float* logits = (const float*)d_in[1];
    const float* mask   = (const float*)d_in[2];
    const float* gains  = (const float*)d_in[3];
    const float* ibasis = (const float*)d_in[4];
    const float* obasis = (const float*)d_in[5];
    const float* refl   = (const float*)d_in[6];
    float* out = (float*)d_out;

    cudaFuncSetAttribute(gemm1_kernel, cudaFuncAttributeMaxDynamicSharedMemorySize, G1_SMEM);
    cudaFuncSetAttribute(delta_kernel, cudaFuncAttributeMaxDynamicSharedMemorySize, G2_SMEM);
    cudaFuncSetAttribute(gemm2_kernel, cudaFuncAttributeMaxDynamicSharedMemorySize, G2_SMEM);

    setup_kernel<<<Bz, 256>>>(logits, mask, gains, refl);
    conv_basis_kernel<<<512, 256>>>(ibasis);
    conv_w_kernel<<<64, 256>>>(obasis);
    gemm1_kernel<<<128, 256, G1_SMEM>>>(x);
    delta_kernel<<<64, 256, G2_SMEM>>>();
    gemm2_kernel<<<dim3(32, 64), 256, G2_SMEM>>>(out);
}